// round 8
// baseline (speedup 1.0000x reference)
#include <cuda_runtime.h>
#include <cstdint>

#define NQ     4
#define IMG    576
#define BN_EPS 1e-5f

// static scratch (no allocation)
__device__ float g_partials[1024 * 8];
__device__ float g_scale[4];
__device__ float g_shift[4];

// ---------------- fused pool + circuit + partial-stats: pure per-thread streaming ----------------
__global__ void __launch_bounds__(128, 8) k_main(
    const float* __restrict__ x,
    const float* __restrict__ enc_w,   // (4,16)
    const float* __restrict__ enc_b,   // (4,)
    const float* __restrict__ qp,      // (2,4)
    float* __restrict__ zout)          // (B,4)
{
    const int t   = threadIdx.x;
    const int s   = blockIdx.x * 128 + t;      // one sample per thread
    const float4* p = (const float4*)(x + (size_t)s * IMG);

    float enc[NQ];
#pragma unroll
    for (int k = 0; k < NQ; k++) enc[k] = __ldg(enc_b + k);

    // ---- stream 24x24 image: 4 bin-rows of (6 rows x 24 cols) ----
#pragma unroll 1
    for (int br = 0; br < 4; br++) {
        float b0 = 0.f, b1 = 0.f, b2 = 0.f, b3 = 0.f;
#pragma unroll
        for (int row = 0; row < 6; row++) {
            float4 r0 = p[0], r1 = p[1], r2 = p[2], r3 = p[3], r4 = p[4], r5 = p[5];
            p += 6;
            b0 += (r0.x + r0.y) + (r0.z + r0.w) + (r1.x + r1.y);
            b1 += (r1.z + r1.w) + (r2.x + r2.y) + (r2.z + r2.w);
            b2 += (r3.x + r3.y) + (r3.z + r3.w) + (r4.x + r4.y);
            b3 += (r4.z + r4.w) + (r5.x + r5.y) + (r5.z + r5.w);
        }
        b0 *= (1.0f / 36.0f); b1 *= (1.0f / 36.0f);
        b2 *= (1.0f / 36.0f); b3 *= (1.0f / 36.0f);
        const int c = br * 4;
#pragma unroll
        for (int k = 0; k < NQ; k++) {
            enc[k] += b0 * __ldg(enc_w + k * 16 + c)
                    + b1 * __ldg(enc_w + k * 16 + c + 1)
                    + b2 * __ldg(enc_w + k * 16 + c + 2)
                    + b3 * __ldg(enc_w + k * 16 + c + 3);
        }
    }

    // ---- statevector circuit in registers ----
    float sx[16], sy[16];
#pragma unroll
    for (int i = 0; i < 16; i++) { sx[i] = 0.f; sy[i] = 0.f; }
    sx[0] = 1.f;

#pragma unroll
    for (int layer = 0; layer < 2; layer++) {
#pragma unroll
        for (int q = 0; q < NQ; q++) {
            const int st = 8 >> q;
            float c, sn;
            __sincosf(0.5f * enc[q], &sn, &c);
#pragma unroll
            for (int i = 0; i < 16; i++) {
                if ((i & st) == 0) {
                    const int j = i | st;
                    float ax = sx[i], ay = sy[i];
                    float bx = sx[j], by = sy[j];
                    sx[i] = c * ax - sn * bx;  sy[i] = c * ay - sn * by;
                    sx[j] = sn * ax + c * bx;  sy[j] = sn * ay + c * by;
                }
            }
            float hc, hs;
            __sincosf(0.5f * __ldg(qp + layer * NQ + q), &hs, &hc);
#pragma unroll
            for (int i = 0; i < 16; i++) {
                float xx = sx[i], yy = sy[i];
                if (i & st) { sx[i] = xx * hc - yy * hs;  sy[i] = yy * hc + xx * hs; }
                else        { sx[i] = xx * hc + yy * hs;  sy[i] = yy * hc - xx * hs; }
            }
        }
        {   // composed CNOT ring permutation (register rename)
            constexpr int P[16] = {0, 13, 3, 14, 6, 11, 5, 8, 12, 1, 15, 2, 10, 7, 9, 4};
            float tx[16], ty[16];
#pragma unroll
            for (int i = 0; i < 16; i++) { tx[i] = sx[i]; ty[i] = sy[i]; }
#pragma unroll
            for (int i = 0; i < 16; i++) { sx[i] = tx[P[i]]; sy[i] = ty[P[i]]; }
        }
    }

    // ---- Z expectations ----
    float z0 = 0.f, z1 = 0.f, z2 = 0.f, z3 = 0.f;
#pragma unroll
    for (int i = 0; i < 16; i++) {
        float p2 = sx[i] * sx[i] + sy[i] * sy[i];
        z0 += ((i >> 3) & 1) ? -p2 : p2;
        z1 += ((i >> 2) & 1) ? -p2 : p2;
        z2 += ((i >> 1) & 1) ? -p2 : p2;
        z3 += ( i       & 1) ? -p2 : p2;
    }

    *(float4*)(zout + (size_t)s * 4) = make_float4(z0, z1, z2, z3);

    // ---- deterministic block (sum, sumsq): warp shuffle + tiny smem tree ----
    float v[8] = {z0, z1, z2, z3, z0 * z0, z1 * z1, z2 * z2, z3 * z3};
#pragma unroll
    for (int off = 16; off >= 1; off >>= 1)
#pragma unroll
        for (int j = 0; j < 8; j++)
            v[j] += __shfl_xor_sync(0xffffffffu, v[j], off);

    __shared__ float sred[4][8];
    const int wid = t >> 5, lid = t & 31;
    if (lid == 0)
#pragma unroll
        for (int j = 0; j < 8; j++) sred[wid][j] = v[j];
    __syncthreads();
    if (t < 8) {
        float a = sred[0][t] + sred[1][t] + sred[2][t] + sred[3][t];
        g_partials[(size_t)blockIdx.x * 8 + t] = a;
    }
}

// ---------------- stats ----------------
__global__ void k_stats(const float* __restrict__ bnw,
                        const float* __restrict__ bnb,
                        int nblk, int B)
{
    __shared__ float s[256];
    const int t    = threadIdx.x;
    const int stat = t & 7;
    const int g    = t >> 3;
    float acc = 0.f;
    for (int i = g; i < nblk; i += 32)
        acc += g_partials[(size_t)i * 8 + stat];
    s[t] = acc;
    __syncthreads();
#pragma unroll
    for (int off = 128; off >= 8; off >>= 1) {
        if (t < off) s[t] += s[t + off];
        __syncthreads();
    }
    if (t < 4) {
        float invB = 1.0f / (float)B;
        float mean = s[t] * invB;
        float var  = s[4 + t] * invB - mean * mean;
        float inv  = rsqrtf(var + BN_EPS);
        float sc   = inv * __ldg(bnw + t);
        g_scale[t] = sc;
        g_shift[t] = __ldg(bnb + t) - mean * sc;
    }
}

// ---------------- normalize ----------------
__global__ void __launch_bounds__(256) k_norm(float* __restrict__ zout, int n4)
{
    const float4 sc = make_float4(g_scale[0], g_scale[1], g_scale[2], g_scale[3]);
    const float4 sh = make_float4(g_shift[0], g_shift[1], g_shift[2], g_shift[3]);
    const int base   = blockIdx.x * 256 + threadIdx.x;
    const int stride = gridDim.x * 256;

    float4 v[4];
    int idx[4];
#pragma unroll
    for (int k = 0; k < 4; k++) {
        idx[k] = base + k * stride;
        if (idx[k] < n4) v[k] = ((float4*)zout)[idx[k]];
    }
#pragma unroll
    for (int k = 0; k < 4; k++) {
        if (idx[k] < n4) {
            float4 z = v[k];
            z.x = z.x * sc.x + sh.x;
            z.y = z.y * sc.y + sh.y;
            z.z = z.z * sc.z + sh.z;
            z.w = z.w * sc.w + sh.w;
            ((float4*)zout)[idx[k]] = z;
        }
    }
}

extern "C" void kernel_launch(void* const* d_in, const int* in_sizes, int n_in,
                              void* d_out, int out_size)
{
    const float* x     = (const float*)d_in[0];
    const float* enc_w = (const float*)d_in[1];
    const float* enc_b = (const float*)d_in[2];
    const float* qp    = (const float*)d_in[3];
    const float* bnw   = (const float*)d_in[4];
    const float* bnb   = (const float*)d_in[5];
    float* out = (float*)d_out;

    int B    = in_sizes[0] / IMG;   // 131072
    int nblk = B / 128;             // 1024

    k_main<<<nblk, 128>>>(x, enc_w, enc_b, qp, out);
    k_stats<<<1, 256>>>(bnw, bnb, nblk, B);
    k_norm<<<128, 256>>>(out, B);
}

// round 9
// speedup vs baseline: 1.2459x; 1.2459x over previous
#include <cuda_runtime.h>
#include <cstdint>

#define NQ     4
#define IMG    576
#define TPB    256
#define NW     8
#define BN_EPS 1e-5f

// static scratch (no allocation)
__device__ float g_partials[1024 * 8];
__device__ float g_scale[4];
__device__ float g_shift[4];

__device__ __forceinline__ void cp_async16(uint32_t smem_addr, const void* gptr) {
    asm volatile("cp.async.cg.shared.global [%0], [%1], 16;\n" :: "r"(smem_addr), "l"(gptr));
}
#define CP_COMMIT() asm volatile("cp.async.commit_group;\n" ::: "memory")
#define CP_WAIT1()  asm volatile("cp.async.wait_group 1;\n" ::: "memory")

// ---------------- fused pool + circuit + partial-stats: warp-autonomous pipelines ----------------
__global__ void __launch_bounds__(TPB, 4) k_main(
    const float* __restrict__ x,
    const float* __restrict__ enc_w,   // (4,16)
    const float* __restrict__ enc_b,   // (4,)
    const float* __restrict__ qp,      // (2,4)
    float* __restrict__ zout,          // (B,4)
    int Btot)
{
    __shared__ float slab[NW][2][IMG];   // 36864 B
    __shared__ float sred[8][8];

    const int t    = threadIdx.x;
    const int w    = t >> 5, l = t & 31;
    const int blk  = blockIdx.x;
    const int nblk = gridDim.x;

    // block slice, then warp slice (balanced +-1)
    const int bs = (int)((long long)blk * Btot / nblk);
    const int be = (int)((long long)(blk + 1) * Btot / nblk);
    const int ws = bs + (int)((long long)w * (be - bs) / NW);
    const int we = bs + (int)((long long)(w + 1) * (be - bs) / NW);
    const int cnt = we - ws;             // <= 32

    uint32_t sb[2];
    sb[0] = (uint32_t)__cvta_generic_to_shared(&slab[w][0][0]);
    sb[1] = (uint32_t)__cvta_generic_to_shared(&slab[w][1][0]);

    // pooling role: 2 lanes per bin
    const int b  = l >> 1, h = l & 1;
    const int rb = b >> 2, cb = b & 3;
    const int poff = rb * 144 + cb * 6 + h * 72;   // floats into slab

    // loop-invariant weights/bias
    float wv[NQ], bb[NQ];
#pragma unroll
    for (int k = 0; k < NQ; k++) {
        wv[k] = __ldg(enc_w + k * 16 + b);
        bb[k] = __ldg(enc_b + k);
    }
    float enc[NQ];
#pragma unroll
    for (int k = 0; k < NQ; k++) enc[k] = bb[k];

    // prologue: issue samples ws+0, ws+1
#pragma unroll
    for (int j = 0; j < 2; j++) {
        if (j < cnt) {
            const float4* src = (const float4*)(x + (size_t)(ws + j) * IMG);
            uint32_t base = sb[j];
#pragma unroll
            for (int k = 0; k < 4; k++)
                cp_async16(base + (uint32_t)(l + 32 * k) * 16u, src + l + 32 * k);
            if (l < 16)
                cp_async16(base + (uint32_t)(128 + l) * 16u, src + 128 + l);
        }
        CP_COMMIT();
    }

#pragma unroll 1
    for (int j = 0; j < cnt; j++) {
        CP_WAIT1();                 // group j complete
        __syncwarp();

        // pool sample j from slab[w][j&1]
        const float* sp = &slab[w][j & 1][0] + poff;
        float2 acc = make_float2(0.f, 0.f);
#pragma unroll
        for (int dr = 0; dr < 3; dr++) {
            const float2* p2 = (const float2*)(sp + dr * 24);
            float2 a = p2[0], c = p2[1], d = p2[2];
            acc.x += a.x + c.x + d.x;
            acc.y += a.y + c.y + d.y;
        }
        float pv = (acc.x + acc.y) * (1.0f / 36.0f);

        float c0 = pv * wv[0], c1 = pv * wv[1], c2 = pv * wv[2], c3 = pv * wv[3];
#pragma unroll
        for (int off = 16; off >= 1; off >>= 1) {
            c0 += __shfl_xor_sync(0xffffffffu, c0, off);
            c1 += __shfl_xor_sync(0xffffffffu, c1, off);
            c2 += __shfl_xor_sync(0xffffffffu, c2, off);
            c3 += __shfl_xor_sync(0xffffffffu, c3, off);
        }
        if (l == j) {
            enc[0] = c0 + bb[0]; enc[1] = c1 + bb[1];
            enc[2] = c2 + bb[2]; enc[3] = c3 + bb[3];
        }
        __syncwarp();               // reads of slab done before refill

        // refill freed buffer with sample j+2
        if (j + 2 < cnt) {
            const float4* src = (const float4*)(x + (size_t)(ws + j + 2) * IMG);
            uint32_t base = sb[j & 1];
#pragma unroll
            for (int k = 0; k < 4; k++)
                cp_async16(base + (uint32_t)(l + 32 * k) * 16u, src + l + 32 * k);
            if (l < 16)
                cp_async16(base + (uint32_t)(128 + l) * 16u, src + 128 + l);
        }
        CP_COMMIT();                // exactly one group per iter
    }

    const bool active = (l < cnt);

    // ---- statevector circuit in registers ----
    float sx[16], sy[16];
#pragma unroll
    for (int i = 0; i < 16; i++) { sx[i] = 0.f; sy[i] = 0.f; }
    sx[0] = 1.f;

#pragma unroll
    for (int layer = 0; layer < 2; layer++) {
#pragma unroll
        for (int q = 0; q < NQ; q++) {
            const int st = 8 >> q;
            float c, sn;
            __sincosf(0.5f * enc[q], &sn, &c);
#pragma unroll
            for (int i = 0; i < 16; i++) {
                if ((i & st) == 0) {
                    const int j = i | st;
                    float ax = sx[i], ay = sy[i];
                    float bx = sx[j], by = sy[j];
                    sx[i] = c * ax - sn * bx;  sy[i] = c * ay - sn * by;
                    sx[j] = sn * ax + c * bx;  sy[j] = sn * ay + c * by;
                }
            }
            float hc, hs;
            __sincosf(0.5f * __ldg(qp + layer * NQ + q), &hs, &hc);
#pragma unroll
            for (int i = 0; i < 16; i++) {
                float xx = sx[i], yy = sy[i];
                if (i & st) { sx[i] = xx * hc - yy * hs;  sy[i] = yy * hc + xx * hs; }
                else        { sx[i] = xx * hc + yy * hs;  sy[i] = yy * hc - xx * hs; }
            }
        }
        {   // composed CNOT ring permutation (register rename)
            constexpr int P[16] = {0, 13, 3, 14, 6, 11, 5, 8, 12, 1, 15, 2, 10, 7, 9, 4};
            float tx[16], ty[16];
#pragma unroll
            for (int i = 0; i < 16; i++) { tx[i] = sx[i]; ty[i] = sy[i]; }
#pragma unroll
            for (int i = 0; i < 16; i++) { sx[i] = tx[P[i]]; sy[i] = ty[P[i]]; }
        }
    }

    // ---- Z expectations (masked for lanes without a sample) ----
    float z0 = 0.f, z1 = 0.f, z2 = 0.f, z3 = 0.f;
    if (active) {
#pragma unroll
        for (int i = 0; i < 16; i++) {
            float p2 = sx[i] * sx[i] + sy[i] * sy[i];
            z0 += ((i >> 3) & 1) ? -p2 : p2;
            z1 += ((i >> 2) & 1) ? -p2 : p2;
            z2 += ((i >> 1) & 1) ? -p2 : p2;
            z3 += ( i       & 1) ? -p2 : p2;
        }
        *(float4*)(zout + (size_t)(ws + l) * 4) = make_float4(z0, z1, z2, z3);
    }

    // ---- deterministic block (sum, sumsq) ----
    float v[8] = {z0, z1, z2, z3, z0 * z0, z1 * z1, z2 * z2, z3 * z3};
#pragma unroll
    for (int off = 16; off >= 1; off >>= 1)
#pragma unroll
        for (int j = 0; j < 8; j++)
            v[j] += __shfl_xor_sync(0xffffffffu, v[j], off);

    if (l == 0)
#pragma unroll
        for (int j = 0; j < 8; j++) sred[w][j] = v[j];
    __syncthreads();
    if (t < 8) {
        float a = 0.f;
#pragma unroll
        for (int ww = 0; ww < 8; ww++) a += sred[ww][t];
        g_partials[(size_t)blk * 8 + t] = a;
    }
}

// ---------------- stats ----------------
__global__ void k_stats(const float* __restrict__ bnw,
                        const float* __restrict__ bnb,
                        int nblk, int B)
{
    __shared__ float s[256];
    const int t    = threadIdx.x;
    const int stat = t & 7;
    const int g    = t >> 3;
    float acc = 0.f;
    for (int i = g; i < nblk; i += 32)
        acc += g_partials[(size_t)i * 8 + stat];
    s[t] = acc;
    __syncthreads();
#pragma unroll
    for (int off = 128; off >= 8; off >>= 1) {
        if (t < off) s[t] += s[t + off];
        __syncthreads();
    }
    if (t < 4) {
        float invB = 1.0f / (float)B;
        float mean = s[t] * invB;
        float var  = s[4 + t] * invB - mean * mean;
        float inv  = rsqrtf(var + BN_EPS);
        float sc   = inv * __ldg(bnw + t);
        g_scale[t] = sc;
        g_shift[t] = __ldg(bnb + t) - mean * sc;
    }
}

// ---------------- normalize ----------------
__global__ void __launch_bounds__(256) k_norm(float* __restrict__ zout, int n4)
{
    const float4 sc = make_float4(g_scale[0], g_scale[1], g_scale[2], g_scale[3]);
    const float4 sh = make_float4(g_shift[0], g_shift[1], g_shift[2], g_shift[3]);
    const int base   = blockIdx.x * 256 + threadIdx.x;
    const int stride = gridDim.x * 256;

    float4 v[4];
    int idx[4];
#pragma unroll
    for (int k = 0; k < 4; k++) {
        idx[k] = base + k * stride;
        if (idx[k] < n4) v[k] = ((float4*)zout)[idx[k]];
    }
#pragma unroll
    for (int k = 0; k < 4; k++) {
        if (idx[k] < n4) {
            float4 z = v[k];
            z.x = z.x * sc.x + sh.x;
            z.y = z.y * sc.y + sh.y;
            z.z = z.z * sc.z + sh.z;
            z.w = z.w * sc.w + sh.w;
            ((float4*)zout)[idx[k]] = z;
        }
    }
}

extern "C" void kernel_launch(void* const* d_in, const int* in_sizes, int n_in,
                              void* d_out, int out_size)
{
    const float* x     = (const float*)d_in[0];
    const float* enc_w = (const float*)d_in[1];
    const float* enc_b = (const float*)d_in[2];
    const float* qp    = (const float*)d_in[3];
    const float* bnw   = (const float*)d_in[4];
    const float* bnb   = (const float*)d_in[5];
    float* out = (float*)d_out;

    int B    = in_sizes[0] / IMG;   // 131072
    int nblk = 592;                 // 148 SMs x 4 blocks

    k_main<<<nblk, TPB>>>(x, enc_w, enc_b, qp, out, B);
    k_stats<<<1, 256>>>(bnw, bnb, nblk, B);
    k_norm<<<128, 256>>>(out, B);
}

// round 10
// speedup vs baseline: 1.2773x; 1.0252x over previous
#include <cuda_runtime.h>
#include <cstdint>

#define NQ     4
#define IMG    576
#define TPB    256
#define SPR    4                 // samples per round
#define NBUF   4                 // ring depth
#define RBYTES (SPR * IMG * 4)   // 9216 B per round
#define BN_EPS 1e-5f

// static scratch (no allocation)
__device__ float g_partials[1024 * 8];
__device__ float g_scale[4];
__device__ float g_shift[4];

__device__ __forceinline__ void mbar_init(uint32_t mbar, uint32_t cnt) {
    asm volatile("mbarrier.init.shared.b64 [%0], %1;" :: "r"(mbar), "r"(cnt) : "memory");
}
__device__ __forceinline__ void mbar_expect_tx(uint32_t mbar, uint32_t bytes) {
    asm volatile("mbarrier.arrive.expect_tx.shared.b64 _, [%0], %1;" :: "r"(mbar), "r"(bytes) : "memory");
}
__device__ __forceinline__ void mbar_wait(uint32_t mbar, uint32_t parity) {
    uint32_t done = 0;
    while (!done) {
        asm volatile(
            "{\n\t.reg .pred p;\n\t"
            "mbarrier.try_wait.parity.acquire.cta.shared::cta.b64 p, [%1], %2, 0x989680;\n\t"
            "selp.b32 %0, 1, 0, p;\n\t}"
            : "=r"(done) : "r"(mbar), "r"(parity) : "memory");
    }
}
__device__ __forceinline__ void tma_bulk(uint32_t dst, const void* src, uint32_t bytes, uint32_t mbar) {
    asm volatile(
        "cp.async.bulk.shared::cta.global.mbarrier::complete_tx::bytes [%0], [%1], %2, [%3];"
        :: "r"(dst), "l"(src), "r"(bytes), "r"(mbar) : "memory");
}

// ---------------- fused pool + circuit + partial-stats (TMA bulk ring) ----------------
__global__ void __launch_bounds__(TPB, 4) k_main(
    const float* __restrict__ x,
    const float* __restrict__ enc_w,   // (4,16)
    const float* __restrict__ enc_b,   // (4,)
    const float* __restrict__ qp,      // (2,4)
    float* __restrict__ zout,          // (B,4)
    int R_total)
{
    __shared__ __align__(128) float stage[NBUF][SPR * IMG];  // 36864 B
    __shared__ float pr[NBUF][SPR][17];
    __shared__ float sred[8][8];
    __shared__ __align__(8) unsigned long long mbar_s[NBUF];

    const int t    = threadIdx.x;
    const int blk  = blockIdx.x;
    const int nblk = gridDim.x;

    const int r0 = (int)((long long)blk * R_total / nblk);
    const int r1 = (int)((long long)(blk + 1) * R_total / nblk);
    const int n  = r1 - r0;                           // <= 64

    const float* xg = x + (size_t)r0 * SPR * IMG;

    uint32_t mb[NBUF], sbuf[NBUF];
#pragma unroll
    for (int j = 0; j < NBUF; j++) {
        mb[j]   = (uint32_t)__cvta_generic_to_shared(&mbar_s[j]);
        sbuf[j] = (uint32_t)__cvta_generic_to_shared(&stage[j][0]);
    }

    if (t == 0) {
#pragma unroll
        for (int j = 0; j < NBUF; j++) mbar_init(mb[j], 1u);
    }
    __syncthreads();

    // prologue: issue rounds 0..2
    if (t == 0) {
#pragma unroll
        for (int j = 0; j < 3; j++) {
            if (j < n) {
                mbar_expect_tx(mb[j], RBYTES);
                tma_bulk(sbuf[j], xg + (size_t)j * SPR * IMG, RBYTES, mb[j]);
            }
        }
    }

    float enc[NQ];
#pragma unroll
    for (int k = 0; k < NQ; k++) enc[k] = __ldg(enc_b + k);

#pragma unroll 1
    for (int r = 0; r < n; r++) {
        __syncthreads();   // buffer (r+3)&3 free (read in r-1); pr[(r-1)&3] visible

        // refill round r+3 (single instruction, thread 0)
        if (t == 0 && r + 3 < n) {
            mbar_expect_tx(mb[(r + 3) & 3], RBYTES);
            tma_bulk(sbuf[(r + 3) & 3], xg + (size_t)(r + 3) * SPR * IMG, RBYTES, mb[(r + 3) & 3]);
        }

        // pool round r: rotating 2-warp duty
        {
            int tp = t - ((r & 3) << 6);
            if ((unsigned)tp < 64u) {
                mbar_wait(mb[r & 3], (uint32_t)((r >> 2) & 1));
                int s  = tp >> 4, b = tp & 15;
                int rb = b >> 2, cb = b & 3;
                const float* bp = &stage[r & 3][0] + s * IMG + rb * 144 + cb * 6;
                float acc = 0.f;
#pragma unroll
                for (int dr = 0; dr < 6; dr++) {
                    const float2* p2 = (const float2*)(bp + dr * 24);
                    float2 a = p2[0], c = p2[1], d = p2[2];
                    acc += (a.x + a.y) + (c.x + c.y) + (d.x + d.y);
                }
                pr[r & 3][s][b] = acc * (1.0f / 36.0f);
            }
        }

        // owners of round r-1 fold pooled -> enc
        if (r > 0 && (t >> 2) == r - 1) {
            const float* pv = pr[(r - 1) & 3][t & 3];
#pragma unroll
            for (int k = 0; k < NQ; k++) {
                float a = enc[k];
#pragma unroll
                for (int i = 0; i < 16; i++)
                    a += pv[i] * __ldg(enc_w + k * 16 + i);
                enc[k] = a;
            }
        }
    }

    // drain: fold last round
    __syncthreads();
    if ((t >> 2) == n - 1) {
        const float* pv = pr[(n - 1) & 3][t & 3];
#pragma unroll
        for (int k = 0; k < NQ; k++) {
            float a = enc[k];
#pragma unroll
            for (int i = 0; i < 16; i++)
                a += pv[i] * __ldg(enc_w + k * 16 + i);
            enc[k] = a;
        }
    }

    const bool active = t < 4 * n;

    // ---- statevector circuit in registers ----
    float sx[16], sy[16];
#pragma unroll
    for (int i = 0; i < 16; i++) { sx[i] = 0.f; sy[i] = 0.f; }
    sx[0] = 1.f;

#pragma unroll
    for (int layer = 0; layer < 2; layer++) {
#pragma unroll
        for (int q = 0; q < NQ; q++) {
            const int st = 8 >> q;
            float c, sn;
            __sincosf(0.5f * enc[q], &sn, &c);
#pragma unroll
            for (int i = 0; i < 16; i++) {
                if ((i & st) == 0) {
                    const int j = i | st;
                    float ax = sx[i], ay = sy[i];
                    float bx = sx[j], by = sy[j];
                    sx[i] = c * ax - sn * bx;  sy[i] = c * ay - sn * by;
                    sx[j] = sn * ax + c * bx;  sy[j] = sn * ay + c * by;
                }
            }
            float hc, hs;
            __sincosf(0.5f * __ldg(qp + layer * NQ + q), &hs, &hc);
#pragma unroll
            for (int i = 0; i < 16; i++) {
                float xx = sx[i], yy = sy[i];
                if (i & st) { sx[i] = xx * hc - yy * hs;  sy[i] = yy * hc + xx * hs; }
                else        { sx[i] = xx * hc + yy * hs;  sy[i] = yy * hc - xx * hs; }
            }
        }
        {   // composed CNOT ring permutation (register rename)
            constexpr int P[16] = {0, 13, 3, 14, 6, 11, 5, 8, 12, 1, 15, 2, 10, 7, 9, 4};
            float tx[16], ty[16];
#pragma unroll
            for (int i = 0; i < 16; i++) { tx[i] = sx[i]; ty[i] = sy[i]; }
#pragma unroll
            for (int i = 0; i < 16; i++) { sx[i] = tx[P[i]]; sy[i] = ty[P[i]]; }
        }
    }

    // ---- Z expectations (masked) ----
    float z0 = 0.f, z1 = 0.f, z2 = 0.f, z3 = 0.f;
    if (active) {
#pragma unroll
        for (int i = 0; i < 16; i++) {
            float p2 = sx[i] * sx[i] + sy[i] * sy[i];
            z0 += ((i >> 3) & 1) ? -p2 : p2;
            z1 += ((i >> 2) & 1) ? -p2 : p2;
            z2 += ((i >> 1) & 1) ? -p2 : p2;
            z3 += ( i       & 1) ? -p2 : p2;
        }
        *(float4*)(zout + ((size_t)r0 * SPR + t) * 4) = make_float4(z0, z1, z2, z3);
    }

    // ---- deterministic block (sum, sumsq) ----
    float v[8] = {z0, z1, z2, z3, z0 * z0, z1 * z1, z2 * z2, z3 * z3};
#pragma unroll
    for (int off = 16; off >= 1; off >>= 1)
#pragma unroll
        for (int j = 0; j < 8; j++)
            v[j] += __shfl_xor_sync(0xffffffffu, v[j], off);

    const int wid = t >> 5, lid = t & 31;
    if (lid == 0)
#pragma unroll
        for (int j = 0; j < 8; j++) sred[wid][j] = v[j];
    __syncthreads();
    if (t < 8) {
        float a = 0.f;
#pragma unroll
        for (int w = 0; w < 8; w++) a += sred[w][t];
        g_partials[(size_t)blk * 8 + t] = a;
    }
}

// ---------------- stats ----------------
__global__ void k_stats(const float* __restrict__ bnw,
                        const float* __restrict__ bnb,
                        int nblk, int B)
{
    __shared__ float s[256];
    const int t    = threadIdx.x;
    const int stat = t & 7;
    const int g    = t >> 3;
    float acc = 0.f;
    for (int i = g; i < nblk; i += 32)
        acc += g_partials[(size_t)i * 8 + stat];
    s[t] = acc;
    __syncthreads();
#pragma unroll
    for (int off = 128; off >= 8; off >>= 1) {
        if (t < off) s[t] += s[t + off];
        __syncthreads();
    }
    if (t < 4) {
        float invB = 1.0f / (float)B;
        float mean = s[t] * invB;
        float var  = s[4 + t] * invB - mean * mean;
        float inv  = rsqrtf(var + BN_EPS);
        float sc   = inv * __ldg(bnw + t);
        g_scale[t] = sc;
        g_shift[t] = __ldg(bnb + t) - mean * sc;
    }
}

// ---------------- normalize ----------------
__global__ void __launch_bounds__(256) k_norm(float* __restrict__ zout, int n4)
{
    const float4 sc = make_float4(g_scale[0], g_scale[1], g_scale[2], g_scale[3]);
    const float4 sh = make_float4(g_shift[0], g_shift[1], g_shift[2], g_shift[3]);
    const int base   = blockIdx.x * 256 + threadIdx.x;
    const int stride = gridDim.x * 256;

    float4 v[4];
    int idx[4];
#pragma unroll
    for (int k = 0; k < 4; k++) {
        idx[k] = base + k * stride;
        if (idx[k] < n4) v[k] = ((float4*)zout)[idx[k]];
    }
#pragma unroll
    for (int k = 0; k < 4; k++) {
        if (idx[k] < n4) {
            float4 z = v[k];
            z.x = z.x * sc.x + sh.x;
            z.y = z.y * sc.y + sh.y;
            z.z = z.z * sc.z + sh.z;
            z.w = z.w * sc.w + sh.w;
            ((float4*)zout)[idx[k]] = z;
        }
    }
}

extern "C" void kernel_launch(void* const* d_in, const int* in_sizes, int n_in,
                              void* d_out, int out_size)
{
    const float* x     = (const float*)d_in[0];
    const float* enc_w = (const float*)d_in[1];
    const float* enc_b = (const float*)d_in[2];
    const float* qp    = (const float*)d_in[3];
    const float* bnw   = (const float*)d_in[4];
    const float* bnb   = (const float*)d_in[5];
    float* out = (float*)d_out;

    int B       = in_sizes[0] / IMG;   // 131072
    int R_total = B / SPR;             // 32768
    int nblk    = 592;                 // 148 SMs x 4 blocks
    if (nblk > R_total) nblk = R_total;

    k_main<<<nblk, TPB>>>(x, enc_w, enc_b, qp, out, R_total);
    k_stats<<<1, 256>>>(bnw, bnb, nblk, B);
    k_norm<<<128, 256>>>(out, B);
}